// round 6
// baseline (speedup 1.0000x reference)
#include <cuda_runtime.h>
#include <cuda_bf16.h>
#include <cstdint>
#include <math.h>

// Problem constants (fixed-shape problem)
#define NMAX 50000
#define EMAX 1250000
#define LAT 64
#define HID 128
#define STEPS 5
#define EPSV 1e-6f

// ---------------- scratch (device globals; no allocation allowed) ----------------
__device__ float g_elat[(size_t)EMAX * LAT];     // 320 MB edge latents (CSR order)
__device__ float g_nlatA[(size_t)NMAX * LAT];
__device__ float g_nlatB[(size_t)NMAX * LAT];
__device__ float g_x[(size_t)NMAX * LAT];
__device__ int   g_counts[NMAX];
__device__ int   g_off[NMAX];
__device__ int   g_pos[NMAX];
__device__ int   g_inv[EMAX];     // edge id -> CSR position
__device__ int   g_sperm[EMAX];   // sender id in CSR order

// ---------------- bf16 helpers ----------------
__device__ __forceinline__ void split2(float f0, float f1, uint32_t& hp, uint32_t& lp) {
    asm("cvt.rn.bf16x2.f32 %0, %1, %2;" : "=r"(hp) : "f"(f1), "f"(f0));
    float h0 = __uint_as_float(hp << 16);
    float h1 = __uint_as_float(hp & 0xFFFF0000u);
    float r0 = f0 - h0, r1 = f1 - h1;
    asm("cvt.rn.bf16x2.f32 %0, %1, %2;" : "=r"(lp) : "f"(r1), "f"(r0));
}
__device__ __forceinline__ float bf16lo(uint32_t w) { return __uint_as_float(w << 16); }
__device__ __forceinline__ float bf16hi(uint32_t w) { return __uint_as_float(w & 0xFFFF0000u); }

// mma.sync m16n8k16 row.col bf16 -> f32 accumulate
__device__ __forceinline__ void mma16816(float* c, const uint32_t* a, const uint32_t* b) {
    asm volatile(
        "mma.sync.aligned.m16n8k16.row.col.f32.bf16.bf16.f32 "
        "{%0,%1,%2,%3}, {%4,%5,%6,%7}, {%8,%9}, {%0,%1,%2,%3};"
        : "+f"(c[0]), "+f"(c[1]), "+f"(c[2]), "+f"(c[3])
        : "r"(a[0]), "r"(a[1]), "r"(a[2]), "r"(a[3]), "r"(b[0]), "r"(b[1]));
}

// ---------------- smem layout (byte offsets) ----------------
// W fragments: uint2 per (n, kt, q); row stride FRP uint2 (FRP ≡ 4 mod 16).
// W1: K=128,N=128,FRP=36 ; W2: K=128,N=64,FRP=36 ; W0: K=64,N=128,FRP=20
#define OFF_W1H 0
#define OFF_W1L 36864
#define OFF_W2H 73728
#define OFF_W2L 92160
#define OFF_W0H 110592
#define OFF_W0L 131072
#define OFF_H1H 151552
#define OFF_H1L 168960
#define OFF_H2H 186368          // X (hi) overlays this region during layer 1
#define OFF_H2L 203776          // X (lo) overlay
#define OFF_B0  221184
#define OFF_B1  221696
#define OFF_B2  222208
#define SM_TOTAL 222464

// convert W [K x N] fp32 -> hi/lo bf16 in B-fragment-major layout
template <int K, int N, int FRP>
__device__ __forceinline__ void conv_w_frag(const float* __restrict__ W,
                                            uint16_t* __restrict__ wh,
                                            uint16_t* __restrict__ wl, int tid) {
    for (int idx = tid; idx < K * N; idx += 256) {
        int k = idx / N, n = idx - k * N;
        float w = W[idx];
        __nv_bfloat16 h = __float2bfloat16(w);
        float hf = __bfloat162float(h);
        __nv_bfloat16 l = __float2bfloat16(w - hf);
        int kt = k >> 4, kw = k & 15;
        int j = (kw >= 8) ? 1 : 0;
        int q = (kw & 7) >> 1;
        int half = kw & 1;
        int o = ((n * FRP + kt * 4 + q) << 2) + (j << 1) + half;
        wh[o] = *(uint16_t*)&h;
        wl[o] = *(uint16_t*)&l;
    }
}

// one layer of 3-term split MMA: acc[NT][4] += A[64 x K] @ W[K x N-slice]
template <int KT, int NT>
__device__ __forceinline__ void mma_block(
    const uint32_t* __restrict__ sAh, const uint32_t* __restrict__ sAl, int asw,
    const uint2* __restrict__ sWh, const uint2* __restrict__ sWl, int frp,
    int r0, int nrow0, int g, int q, float acc[NT][4]) {
    #pragma unroll
    for (int nt = 0; nt < NT; nt++)
        #pragma unroll
        for (int j = 0; j < 4; j++) acc[nt][j] = 0.f;

    #pragma unroll
    for (int kt = 0; kt < KT; kt++) {
        int k0 = kt * 8;
        const uint32_t* ar0 = sAh + (r0 + g) * asw + k0 + q;
        const uint32_t* ar1 = sAh + (r0 + g + 8) * asw + k0 + q;
        uint32_t ah[4] = { ar0[0], ar1[0], ar0[4], ar1[4] };
        const uint32_t* al0 = sAl + (r0 + g) * asw + k0 + q;
        const uint32_t* al1 = sAl + (r0 + g + 8) * asw + k0 + q;
        uint32_t al[4] = { al0[0], al1[0], al0[4], al1[4] };
        #pragma unroll
        for (int nt = 0; nt < NT; nt++) {
            int fi = (nrow0 + nt * 8 + g) * frp + kt * 4 + q;
            uint2 bhv = sWh[fi];
            uint2 blv = sWl[fi];
            uint32_t bh[2] = { bhv.x, bhv.y };
            uint32_t bl[2] = { blv.x, blv.y };
            mma16816(acc[nt], ah, bh);
            mma16816(acc[nt], al, bh);
            mma16816(acc[nt], ah, bl);
        }
    }
}

// epilogue: bias + relu + hi/lo split -> activation buffers (stride dsw words)
template <int NT>
__device__ __forceinline__ void epi_store_act(
    float acc[NT][4], const float* __restrict__ bias,
    uint32_t* __restrict__ dh, uint32_t* __restrict__ dl, int dsw,
    int r0, int ncol0, int g, int q) {
    #pragma unroll
    for (int nt = 0; nt < NT; nt++) {
        int c0 = ncol0 + nt * 8 + 2 * q;
        float b0v = bias[c0], b1v = bias[c0 + 1];
        int w = c0 >> 1;
        uint32_t h, l;
        float f0 = fmaxf(acc[nt][0] + b0v, 0.f);
        float f1 = fmaxf(acc[nt][1] + b1v, 0.f);
        split2(f0, f1, h, l);
        dh[(r0 + g) * dsw + w] = h;
        dl[(r0 + g) * dsw + w] = l;
        float f2 = fmaxf(acc[nt][2] + b0v, 0.f);
        float f3 = fmaxf(acc[nt][3] + b1v, 0.f);
        split2(f2, f3, h, l);
        dh[(r0 + g + 8) * dsw + w] = h;
        dl[(r0 + g + 8) * dsw + w] = l;
    }
}

// ---------------- fused 3-layer MLP on mma.sync (HMMA) ----------------
template <int DIN, int DOUT, bool FINAL_MASK>
__global__ void __launch_bounds__(256, 1)
mlp3_hmma(const float* __restrict__ X,
          const float* __restrict__ W0, const float* __restrict__ b0,
          const float* __restrict__ W1, const float* __restrict__ b1,
          const float* __restrict__ W2, const float* __restrict__ b2,
          float* __restrict__ Y, int M, const float* __restrict__ masksrc,
          const int* __restrict__ rowmap) {
    extern __shared__ char smem[];
    uint2* sW1h = (uint2*)(smem + OFF_W1H);
    uint2* sW1l = (uint2*)(smem + OFF_W1L);
    uint2* sW2h = (uint2*)(smem + OFF_W2H);
    uint2* sW2l = (uint2*)(smem + OFF_W2L);
    uint2* sW0h = (uint2*)(smem + OFF_W0H);
    uint2* sW0l = (uint2*)(smem + OFF_W0L);
    uint32_t* sH1h = (uint32_t*)(smem + OFF_H1H);
    uint32_t* sH1l = (uint32_t*)(smem + OFF_H1L);
    uint32_t* sH2h = (uint32_t*)(smem + OFF_H2H);
    uint32_t* sH2l = (uint32_t*)(smem + OFF_H2L);
    uint32_t* sXh  = sH2h;    // X overlays H2 (X consumed before H2 written)
    uint32_t* sXl  = sH2l;
    float* sb0 = (float*)(smem + OFF_B0);
    float* sb1 = (float*)(smem + OFF_B1);
    float* sb2 = (float*)(smem + OFF_B2);
    float* sW0f = (float*)(smem + OFF_W0H);   // fp32 W0 when DIN small
    float* sW2f = (float*)(smem + OFF_W2H);   // fp32 W2 when DOUT small

    int tid = threadIdx.x;

    // ---- weights -> smem ----
    if constexpr (DIN >= 16)
        conv_w_frag<64, 128, 20>(W0, (uint16_t*)sW0h, (uint16_t*)sW0l, tid);
    else
        for (int i = tid; i < DIN * 128; i += 256) sW0f[i] = W0[i];
    conv_w_frag<128, 128, 36>(W1, (uint16_t*)sW1h, (uint16_t*)sW1l, tid);
    if constexpr (DOUT >= 16)
        conv_w_frag<128, 64, 36>(W2, (uint16_t*)sW2h, (uint16_t*)sW2l, tid);
    else
        for (int i = tid; i < 128 * DOUT; i += 256) sW2f[i] = W2[i];
    if (tid < 128) { sb0[tid] = b0[tid]; sb1[tid] = b1[tid]; }
    if (tid < DOUT) sb2[tid] = b2[tid];
    __syncthreads();

    int lane = tid & 31, wid = tid >> 5;
    int g = lane >> 2, q = lane & 3;
    int strip = wid & 3;       // rows strip*16
    int nh = wid >> 2;         // 0/1 (N-half)
    int r0 = strip * 16;

    int ntiles = (M + 63) >> 6;
    for (int tile = blockIdx.x; tile < ntiles; tile += gridDim.x) {
        int row0 = tile << 6;

        // ---- layer 1 ----
        if constexpr (DIN >= 16) {
            // stage X [64 x 64] fp32 -> sXh/sXl (hi/lo bf16), stride 36 words
            {
                int r = tid >> 2, c16 = (tid & 3) * 16;
                int gr = row0 + r;
                const float2* src = (const float2*)(X + (size_t)gr * 64 + c16);
                #pragma unroll
                for (int jj = 0; jj < 8; jj++) {
                    float2 v = (gr < M) ? src[jj] : make_float2(0.f, 0.f);
                    uint32_t h, l;
                    split2(v.x, v.y, h, l);
                    int w = r * 36 + (c16 >> 1) + jj;
                    sXh[w] = h; sXl[w] = l;
                }
            }
            __syncthreads();
            float acc[8][4];
            mma_block<4, 8>(sXh, sXl, 36, sW0h, sW0l, 20, r0, nh * 64, g, q, acc);
            __syncthreads();   // X (=H2 region) fully consumed before layer-2 epi writes H2
            epi_store_act<8>(acc, sb0, sH1h, sH1l, 68, r0, nh * 64, g, q);
            __syncthreads();
        } else {
            // scalar layer 1 (K = 2 or 3)
            int r = tid >> 2, cbase = (tid & 3) * 32;
            int gr = row0 + r;
            float x0 = 0.f, x1 = 0.f, x2 = 0.f;
            if (gr < M) {
                x0 = X[(size_t)gr * DIN];
                x1 = X[(size_t)gr * DIN + 1];
                if (DIN > 2) x2 = X[(size_t)gr * DIN + 2];
            }
            #pragma unroll
            for (int jj = 0; jj < 16; jj++) {
                int c = cbase + jj * 2;
                float f0 = sb0[c]     + x0 * sW0f[c]       + x1 * sW0f[128 + c];
                float f1 = sb0[c + 1] + x0 * sW0f[c + 1]   + x1 * sW0f[128 + c + 1];
                if (DIN > 2) {
                    f0 += x2 * sW0f[256 + c];
                    f1 += x2 * sW0f[256 + c + 1];
                }
                f0 = fmaxf(f0, 0.f); f1 = fmaxf(f1, 0.f);
                uint32_t h, l;
                split2(f0, f1, h, l);
                sH1h[r * 68 + (c >> 1)] = h;
                sH1l[r * 68 + (c >> 1)] = l;
            }
            __syncthreads();
        }

        // ---- layer 2: [64x128] @ [128x128] -> relu -> H2 ----
        {
            float acc[8][4];
            mma_block<8, 8>(sH1h, sH1l, 68, sW1h, sW1l, 36, r0, nh * 64, g, q, acc);
            epi_store_act<8>(acc, sb1, sH2h, sH2l, 68, r0, nh * 64, g, q);
            __syncthreads();
        }

        // ---- layer 3 ----
        if constexpr (DOUT >= 16) {
            float acc[4][4];
            mma_block<8, 4>(sH2h, sH2l, 68, sW2h, sW2l, 36, r0, nh * 32, g, q, acc);
            int gr0 = row0 + r0 + g;
            int gr1 = gr0 + 8;
            bool ok0 = gr0 < M, ok1 = gr1 < M;
            size_t or0 = 0, or1 = 0;
            if (ok0) or0 = rowmap ? (size_t)rowmap[gr0] : (size_t)gr0;
            if (ok1) or1 = rowmap ? (size_t)rowmap[gr1] : (size_t)gr1;
            #pragma unroll
            for (int nt = 0; nt < 4; nt++) {
                int c0 = nh * 32 + nt * 8 + 2 * q;
                float b0v = sb2[c0], b1v = sb2[c0 + 1];
                if (ok0)
                    *(float2*)(Y + or0 * DOUT + c0) =
                        make_float2(acc[nt][0] + b0v, acc[nt][1] + b1v);
                if (ok1)
                    *(float2*)(Y + or1 * DOUT + c0) =
                        make_float2(acc[nt][2] + b0v, acc[nt][3] + b1v);
            }
            __syncthreads();
        } else {
            // decoder: scalar layer 3 (DOUT = 2), 4 lanes per row
            int r = tid >> 2, ks = (tid & 3) * 32;
            float y0 = 0.f, y1 = 0.f;
            #pragma unroll
            for (int jj = 0; jj < 16; jj++) {
                int kw = (ks >> 1) + jj;
                uint32_t hw = sH2h[r * 68 + kw], lw = sH2l[r * 68 + kw];
                float xe = bf16lo(hw) + bf16lo(lw);
                float xo = bf16hi(hw) + bf16hi(lw);
                int k = ks + jj * 2;
                y0 = fmaf(xe, sW2f[k * 2],           y0);
                y1 = fmaf(xe, sW2f[k * 2 + 1],       y1);
                y0 = fmaf(xo, sW2f[(k + 1) * 2],     y0);
                y1 = fmaf(xo, sW2f[(k + 1) * 2 + 1], y1);
            }
            y0 += __shfl_xor_sync(0xffffffffu, y0, 1);
            y1 += __shfl_xor_sync(0xffffffffu, y1, 1);
            y0 += __shfl_xor_sync(0xffffffffu, y0, 2);
            y1 += __shfl_xor_sync(0xffffffffu, y1, 2);
            int gr = row0 + r;
            if ((tid & 3) == 0 && gr < M) {
                float v0 = y0 + sb2[0], v1 = y1 + sb2[1];
                if (FINAL_MASK) {
                    float a = fabsf(masksrc[(size_t)gr * 2]) +
                              fabsf(masksrc[(size_t)gr * 2 + 1]);
                    if (a == 0.f) { v0 = 0.f; v1 = 0.f; }
                }
                *(float2*)(Y + (size_t)gr * 2) = make_float2(v0, v1);
            }
            __syncthreads();
        }
    }
}

// ---------------- CSR build ----------------
__global__ void zero_counts_kernel(int* counts, int n) {
    int i = blockIdx.x * blockDim.x + threadIdx.x;
    if (i < n) counts[i] = 0;
}

__global__ void hist_kernel(const int* __restrict__ recv, int* __restrict__ counts, int e) {
    int i = blockIdx.x * blockDim.x + threadIdx.x;
    if (i < e) atomicAdd(&counts[recv[i]], 1);
}

__global__ void scan_kernel(const int* __restrict__ counts, int* __restrict__ off,
                            int* __restrict__ pos, int n) {
    __shared__ int sbuf[1024];
    __shared__ int s_carry;
    int t = threadIdx.x;
    if (t == 0) s_carry = 0;
    __syncthreads();
    for (int base = 0; base < n; base += 1024) {
        int i = base + t;
        int v = (i < n) ? counts[i] : 0;
        sbuf[t] = v;
        __syncthreads();
        for (int d = 1; d < 1024; d <<= 1) {
            int y = 0;
            if (t >= d) y = sbuf[t - d];
            __syncthreads();
            if (t >= d) sbuf[t] += y;
            __syncthreads();
        }
        int incl = sbuf[t];
        int carry = s_carry;
        if (i < n) {
            int excl = carry + incl - v;
            off[i] = excl;
            pos[i] = excl;
        }
        __syncthreads();
        if (t == 1023) s_carry = carry + sbuf[1023];
        __syncthreads();
    }
}

__global__ void scatter_kernel(const int* __restrict__ recv, const int* __restrict__ send,
                               int* __restrict__ pos, int* __restrict__ inv,
                               int* __restrict__ sperm, int e) {
    int i = blockIdx.x * blockDim.x + threadIdx.x;
    if (i < e) {
        int r = recv[i];
        int p = atomicAdd(&pos[r], 1);
        inv[i] = p;
        sperm[p] = send[i];
    }
}

// ---------------- GEN aggregation: online softmax, warp-per-node ----------------
// elat is stored in CSR (receiver-sorted) order -> fully sequential reads.
__global__ void agg_kernel(const float* __restrict__ nlat, const float* __restrict__ elat,
                           const int* __restrict__ sperm,
                           const int* __restrict__ off, const int* __restrict__ cnt,
                           float* __restrict__ xout, int n) {
    int warp = (blockIdx.x * blockDim.x + threadIdx.x) >> 5;
    int lane = threadIdx.x & 31;
    if (warp >= n) return;
    int v = warp;
    int start = off[v];
    int c = cnt[v];

    float mx0 = -1e30f, mx1 = -1e30f;
    float s0 = 0.f, s1 = 0.f, t0 = 0.f, t1 = 0.f;

    const float2* ebase = (const float2*)(elat + (size_t)start * LAT) + lane;

    #pragma unroll 2
    for (int j = 0; j < c; j++) {
        int snd = sperm[start + j];
        float2 e2 = ebase[(size_t)j * 32];
        float2 n2 = *((const float2*)(nlat + (size_t)snd * LAT) + lane);
        float m0 = fmaxf(n2.x + e2.x, 0.f) + EPSV;
        float m1 = fmaxf(n2.y + e2.y, 0.f) + EPSV;
        float nm0 = fmaxf(mx0, m0), nm1 = fmaxf(mx1, m1);
        float c0 = __expf(mx0 - nm0), c1 = __expf(mx1 - nm1);
        float x0 = __expf(m0 - nm0), x1 = __expf(m1 - nm1);
        s0 = s0 * c0 + x0; t0 = t0 * c0 + x0 * m0;
        s1 = s1 * c1 + x1; t1 = t1 * c1 + x1 * m1;
        mx0 = nm0; mx1 = nm1;
    }
    float a0 = (c > 0) ? (t0 / s0) : 0.f;
    float a1 = (c > 0) ? (t1 / s1) : 0.f;
    float2 self = *((const float2*)(nlat + (size_t)v * LAT) + lane);
    *((float2*)(xout + (size_t)v * LAT) + lane) = make_float2(self.x + a0, self.y + a1);
}

// ---------------- host ----------------
extern "C" void kernel_launch(void* const* d_in, const int* in_sizes, int n_in,
                              void* d_out, int out_size) {
    const float* nodes = (const float*)d_in[0];
    const float* edges = (const float*)d_in[1];
    const int* senders = (const int*)d_in[2];
    const int* receivers = (const int*)d_in[3];
    const float* enW0 = (const float*)d_in[4];
    const float* enb0 = (const float*)d_in[5];
    const float* enW1 = (const float*)d_in[6];
    const float* enb1 = (const float*)d_in[7];
    const float* enW2 = (const float*)d_in[8];
    const float* enb2 = (const float*)d_in[9];
    const float* eeW0 = (const float*)d_in[10];
    const float* eeb0 = (const float*)d_in[11];
    const float* eeW1 = (const float*)d_in[12];
    const float* eeb1 = (const float*)d_in[13];
    const float* eeW2 = (const float*)d_in[14];
    const float* eeb2 = (const float*)d_in[15];
    const float* pW0 = (const float*)d_in[16];
    const float* pb0 = (const float*)d_in[17];
    const float* pW1 = (const float*)d_in[18];
    const float* pb1 = (const float*)d_in[19];
    const float* pW2 = (const float*)d_in[20];
    const float* pb2 = (const float*)d_in[21];
    const float* dW0 = (const float*)d_in[22];
    const float* db0 = (const float*)d_in[23];
    const float* dW1 = (const float*)d_in[24];
    const float* db1 = (const float*)d_in[25];
    const float* dW2 = (const float*)d_in[26];
    const float* db2 = (const float*)d_in[27];
    float* out = (float*)d_out;

    int n = in_sizes[0] / 2;   // 50000
    int e = in_sizes[2];       // 1250000

    // scratch pointers
    float *p_elat, *p_nlatA, *p_nlatB, *p_x;
    int *p_counts, *p_off, *p_pos, *p_inv, *p_sperm;
    cudaGetSymbolAddress((void**)&p_elat, g_elat);
    cudaGetSymbolAddress((void**)&p_nlatA, g_nlatA);
    cudaGetSymbolAddress((void**)&p_nlatB, g_nlatB);
    cudaGetSymbolAddress((void**)&p_x, g_x);
    cudaGetSymbolAddress((void**)&p_counts, g_counts);
    cudaGetSymbolAddress((void**)&p_off, g_off);
    cudaGetSymbolAddress((void**)&p_pos, g_pos);
    cudaGetSymbolAddress((void**)&p_inv, g_inv);
    cudaGetSymbolAddress((void**)&p_sperm, g_sperm);

    cudaFuncSetAttribute(mlp3_hmma<2, 64, false>,
                         cudaFuncAttributeMaxDynamicSharedMemorySize, SM_TOTAL);
    cudaFuncSetAttribute(mlp3_hmma<3, 64, false>,
                         cudaFuncAttributeMaxDynamicSharedMemorySize, SM_TOTAL);
    cudaFuncSetAttribute(mlp3_hmma<64, 64, false>,
                         cudaFuncAttributeMaxDynamicSharedMemorySize, SM_TOTAL);
    cudaFuncSetAttribute(mlp3_hmma<64, 2, true>,
                         cudaFuncAttributeMaxDynamicSharedMemorySize, SM_TOTAL);

    // ---- CSR build (by receiver) ----
    zero_counts_kernel<<<(n + 255) / 256, 256>>>(p_counts, n);
    hist_kernel<<<(e + 255) / 256, 256>>>(receivers, p_counts, e);
    scan_kernel<<<1, 1024>>>(p_counts, p_off, p_pos, n);
    scatter_kernel<<<(e + 255) / 256, 256>>>(receivers, senders, p_pos,
                                             p_inv, p_sperm, e);

    // ---- encoders (edge encoder writes elat in CSR order via rowmap) ----
    mlp3_hmma<2, 64, false><<<148, 256, SM_TOTAL>>>(
        nodes, enW0, enb0, enW1, enb1, enW2, enb2, p_nlatA, n, nullptr, nullptr);
    mlp3_hmma<3, 64, false><<<148, 256, SM_TOTAL>>>(
        edges, eeW0, eeb0, eeW1, eeb1, eeW2, eeb2, p_elat, e, nullptr, p_inv);

    // ---- processor: 5 GEN message-passing steps ----
    float* cur = p_nlatA;
    float* nxt = p_nlatB;
    int agg_blocks = (n * 32 + 255) / 256;  // one warp per node
    for (int s = 0; s < STEPS; s++) {
        agg_kernel<<<agg_blocks, 256>>>(cur, p_elat, p_sperm,
                                        p_off, p_counts, p_x, n);
        mlp3_hmma<64, 64, false><<<148, 256, SM_TOTAL>>>(
            p_x,
            pW0 + (size_t)s * 64 * 128, pb0 + (size_t)s * 128,
            pW1 + (size_t)s * 128 * 128, pb1 + (size_t)s * 128,
            pW2 + (size_t)s * 128 * 64, pb2 + (size_t)s * 64,
            nxt, n, nullptr, nullptr);
        float* tmp = cur; cur = nxt; nxt = tmp;
    }

    // ---- decoder (+ zero-mask for padded nodes) ----
    mlp3_hmma<64, 2, true><<<148, 256, SM_TOTAL>>>(
        cur, dW0, db0, dW1, db1, dW2, db2, out, n, nodes, nullptr);
}